// round 5
// baseline (speedup 1.0000x reference)
#include <cuda_runtime.h>

#define LSEQ 512
#define BSZ 1024
#define NTAG 64
#define START_TAG 62
#define END_TAG 63

typedef unsigned long long ull;

// ---- packed f32x2 helpers (Blackwell FFMA2: only reachable via PTX) ----
__device__ __forceinline__ ull pack2(float lo, float hi) {
    ull d;
    asm("mov.b64 %0, {%1, %2};" : "=l"(d) : "f"(lo), "f"(hi));
    return d;
}
__device__ __forceinline__ void unpack2(ull v, float& lo, float& hi) {
    asm("mov.b64 {%0, %1}, %2;" : "=f"(lo), "=f"(hi) : "l"(v));
}
__device__ __forceinline__ ull fma2(ull a, ull b, ull c) {
    ull d;
    asm("fma.rn.f32x2 %0, %1, %2, %3;" : "=l"(d) : "l"(a), "l"(b), "l"(c));
    return d;
}
__device__ __forceinline__ ull add2(ull a, ull b) {
    ull d;
    asm("add.rn.f32x2 %0, %1, %2;" : "=l"(d) : "l"(a), "l"(b));
    return d;
}

// ============================================================================
// Fused CRF kernel, K-SPLIT across 2 warps (64-thread block = 1 batch).
//
// Thread owns OUTPUT PAIR (2*lane, 2*lane+1); warp w owns INPUT half
// [32w, 32w+32). Per step, per thread:
//   - 8 LDS.128  : its warp's half of v (natural pairs)
//   - 32 FFMA2   : 4 chains of depth 8 (2 outputs x 16 input-pairs)
//   - STS.64/LDS.64 : cross-warp partial exchange (the only communication)
//   - LDG.64     : feat pair for its two tags (4-step prefetch ring)
// Both warps hold the full new v redundantly -> renorm butterfly is intra-
// warp only; only warp 0 writes v to smem. Renorm every 4 steps, deferred:
// max produced after step l%4==3, consumed (1/hi folded into exp(feat),
// c += log hi) at the next l%4==0 step. 2 x bar.sync(nw=2) per step.
// Realpath (gold score) fused as a block tail. Grid = 1024 -> ~7 blocks/SM.
// ============================================================================
__global__ void __launch_bounds__(64, 7) crf_fused_kernel(
    const float* __restrict__ feats,
    const int*   __restrict__ tags,
    const float* __restrict__ mask,
    const float* __restrict__ transition,
    float* __restrict__ out)
{
    __shared__ __align__(16) float  vbuf[2][NTAG];   // ping-pong v
    __shared__ __align__(16) float2 pbuf[2][32];     // per-warp partials
    __shared__ float redsh[5];                       // allpath, rsum x2, rlen x2

    const int tid  = threadIdx.x;
    const int w    = tid >> 5;
    const int lane = tid & 31;
    const int b    = blockIdx.x;
    const int t0   = 2 * lane;       // output tags owned by this thread
    const int t1   = t0 + 1;
    const int p0   = 32 * w;         // input-half base for this warp

    // eA[j] = (E[t0, p0+2j], E[t0, p0+2j+1]);  eB same for t1.  64 regs.
    ull eA[16], eB[16];
#pragma unroll
    for (int j = 0; j < 16; ++j) {
        eA[j] = pack2(__expf(__ldg(transition + t0 * NTAG + p0 + 2 * j)),
                      __expf(__ldg(transition + t0 * NTAG + p0 + 2 * j + 1)));
        eB[j] = pack2(__expf(__ldg(transition + t1 * NTAG + p0 + 2 * j)),
                      __expf(__ldg(transition + t1 * NTAG + p0 + 2 * j + 1)));
    }

    // v0 = one-hot(START); c = 0; first renorm-consume is a no-op (maxv=1)
    float myv0 = (t0 == START_TAG) ? 1.0f : 0.0f;
    float myv1 = (t1 == START_TAG) ? 1.0f : 0.0f;
    if (w == 0) ((float2*)vbuf[0])[lane] = make_float2(myv0, myv1);
    float c = 0.0f;
    float maxv = 1.0f;
    __syncthreads();

    // 4-step prefetch ring: feat pair (LDG.64) + warp-uniform mask
    const float* fptr = feats + (size_t)b * NTAG + t0;
    float2 fr[4];
    float  mr[4];
#pragma unroll
    for (int u = 0; u < 4; ++u) {
        fr[u] = *(const float2*)(fptr + (size_t)u * (BSZ * NTAG));
        mr[u] = __ldg(mask + u * BSZ + b);
    }

    for (int l4 = 0; l4 < LSEQ; l4 += 4) {
#pragma unroll
        for (int u = 0; u < 4; ++u) {
            const int l = l4 + u;
            const float2 f = fr[u];
            const float  m = mr[u];
            int ln = l + 4;
            if (ln > LSEQ - 1) ln = LSEQ - 1;
            fr[u] = *(const float2*)(fptr + (size_t)ln * (BSZ * NTAG));
            mr[u] = __ldg(mask + ln * BSZ + b);

            // consume deferred renorm; independent of v -> hidden under MV
            float scale = 1.0f;
            if (u == 0) {
                scale = __fdividef(1.0f, maxv);
                c += __logf(maxv);
            }
            const float ef0 = __expf(f.x) * scale;
            const float ef1 = __expf(f.y) * scale;

            // partial MV over this warp's input half: 4 chains of depth 8
            const ulonglong2* vp = (const ulonglong2*)(vbuf[l & 1] + p0);
            ull aA0 = 0ull, aA1 = 0ull, aB0 = 0ull, aB1 = 0ull;
            ulonglong2 wr[4];
#pragma unroll
            for (int j = 0; j < 4; ++j) wr[j] = vp[j];
#pragma unroll
            for (int k = 0; k < 8; ++k) {
                const ulonglong2 cur = wr[k & 3];
                if (k < 4) wr[k & 3] = vp[k + 4];
                aA0 = fma2(eA[2 * k],     cur.x, aA0);
                aB0 = fma2(eB[2 * k],     cur.x, aB0);
                aA1 = fma2(eA[2 * k + 1], cur.y, aA1);
                aB1 = fma2(eB[2 * k + 1], cur.y, aB1);
            }
            const ull sA = add2(aA0, aA1);
            const ull sB = add2(aB0, aB1);
            float sAl, sAh, sBl, sBh;
            unpack2(sA, sAl, sAh);
            unpack2(sB, sBl, sBh);
            const float pt0 = sAl + sAh;
            const float pt1 = sBl + sBh;

            // cross-warp partial exchange
            pbuf[w][lane] = make_float2(pt0, pt1);
            __syncthreads();
            const float2 po = pbuf[w ^ 1][lane];

            float v0n = (pt0 + po.x) * ef0;
            float v1n = (pt1 + po.y) * ef1;
            if (m == 0.0f) { v0n = myv0 * scale; v1n = myv1 * scale; }

            myv0 = v0n;
            myv1 = v1n;
            if (w == 0)
                ((float2*)vbuf[(l & 1) ^ 1])[lane] = make_float2(v0n, v1n);

            if (u == 3) {   // produce next renorm factor (intra-warp: both
                float hi = fmaxf(v0n, v1n);   // warps hold the full v)
#pragma unroll
                for (int o = 16; o > 0; o >>= 1)
                    hi = fmaxf(hi, __shfl_xor_sync(0xffffffffu, hi, o));
                maxv = hi;
            }
            __syncthreads();
        }
    }

    // allpath = c + log( sum_t v[t] * exp(T[END,t]) ); warp 0 has full v
    if (w == 0) {
        float s = myv0 * __expf(__ldg(transition + END_TAG * NTAG + t0))
                + myv1 * __expf(__ldg(transition + END_TAG * NTAG + t1));
#pragma unroll
        for (int o = 16; o > 0; o >>= 1)
            s += __shfl_xor_sync(0xffffffffu, s, o);
        if (lane == 0) redsh[0] = c + __logf(s);
    }

    // ---- realpath tail: 64 threads split L (8 each), independent gathers --
    float rsum = 0.0f, rlen = 0.0f;
#pragma unroll
    for (int i = 0; i < 8; ++i) {
        const int l = tid + 64 * i;
        int tag  = __ldg(tags + l * BSZ + b);
        int prev = (l == 0) ? START_TAG : __ldg(tags + (l - 1) * BSZ + b);
        float m  = __ldg(mask + l * BSZ + b);
        float emit = __ldg(feats + ((size_t)l * BSZ + b) * NTAG + tag);
        float tr   = __ldg(transition + tag * NTAG + prev);
        rsum += (emit + tr) * m;
        rlen += m;
    }
#pragma unroll
    for (int o = 16; o > 0; o >>= 1) {
        rsum += __shfl_xor_sync(0xffffffffu, rsum, o);
        rlen += __shfl_xor_sync(0xffffffffu, rlen, o);
    }
    if (lane == 0) { redsh[1 + w] = rsum; redsh[3 + w] = rlen; }
    __syncthreads();

    if (tid == 0) {
        const float rs = redsh[1] + redsh[2];
        const int length = (int)(redsh[3] + redsh[4] + 0.5f);
        const int last = (length > 0) ? __ldg(tags + (length - 1) * BSZ + b)
                                      : START_TAG;
        const float real = rs + __ldg(transition + END_TAG * NTAG + last);
        out[b] = redsh[0] - real;
    }
}

extern "C" void kernel_launch(void* const* d_in, const int* in_sizes, int n_in,
                              void* d_out, int out_size) {
    const float* feats      = (const float*)d_in[0];
    const int*   tags       = (const int*)  d_in[1];
    const float* mask       = (const float*)d_in[2];
    const float* transition = (const float*)d_in[3];
    float* out = (float*)d_out;

    crf_fused_kernel<<<BSZ, 64>>>(feats, tags, mask, transition, out);
}